// round 3
// baseline (speedup 1.0000x reference)
#include <cuda_runtime.h>
#include <cuda_bf16.h>
#include <math.h>

// Problem constants
#define D     512
#define KMOD  8
#define SSLOT 4
#define BATCH 8192
#define MBIG  (BATCH * KMOD)   // 65536
#define MWS   (BATCH * SSLOT)  // 32768
#define SCALE 0.04419417382415922f   // 512^-0.5
#define LN_EPS 1e-5f

// ---------------- scratch (device globals; allocation-free) ----------------
__device__ float g_Kw[(size_t)MBIG * D];     // later reused for 'broadcast'
__device__ float g_Vw[(size_t)MBIG * D];     // later reused for 'proj'
__device__ float g_Qr[(size_t)MBIG * D];
__device__ float g_wsupd[(size_t)MWS * D];
__device__ float g_Kr[(size_t)MWS * D];
__device__ float g_Vr[(size_t)MWS * D];
__device__ float g_Qw[SSLOT * D];            // pre-scaled slot queries
__device__ unsigned char g_mask[BATCH * KMOD];
__device__ int g_mask_is_i32;

// ---------------- mask dtype sniffing + normalization ----------------------
// The reference produces a bool mask; the harness may store it as int32 or as
// 1-byte bools. Detect by scanning the first 16384 int32 words (64 KB, in
// bounds under either layout): int32 storage => all words in {0,1};
// byte-packed random 0/1 data => words like 0x00000101 appear w.h.p.
__global__ void mask_detect_kernel(const void* __restrict__ mask) {
    const int* mi = (const int*)mask;
    int bad = 0;
    for (int i = threadIdx.x; i < 16384; i += blockDim.x) {
        int v = mi[i];
        if (v != 0 && v != 1) bad = 1;
    }
    bad = __syncthreads_or(bad);
    if (threadIdx.x == 0) g_mask_is_i32 = !bad;
}

__global__ void mask_convert_kernel(const void* __restrict__ mask) {
    int i = blockIdx.x * blockDim.x + threadIdx.x;
    if (i >= BATCH * KMOD) return;
    unsigned char v;
    if (g_mask_is_i32) v = (((const int*)mask)[i] != 0);
    else               v = (((const unsigned char*)mask)[i] != 0);
    g_mask[i] = v;
}

// ---------------- tiny precompute: Qw[s][e] = SCALE * sum_d ws[s,d]*Wq_w[e,d]
__global__ void qw_kernel(const float* __restrict__ workspace,
                          const float* __restrict__ Wq_w) {
    int s = blockIdx.x;          // 0..3
    int e = threadIdx.x;         // 0..511
    __shared__ float wsrow[D];
    wsrow[e] = workspace[s * D + e];
    __syncthreads();
    const float* wrow = Wq_w + (size_t)e * D;
    float acc = 0.f;
#pragma unroll 8
    for (int d = 0; d < D; d++) acc += wsrow[d] * wrow[d];
    g_Qw[s * D + e] = acc * SCALE;
}

// ---------------- SGEMM (NT): C[m,n] = sum_k A[m,k] * W[n,k]; N=K=512 ------
#define BM 128
#define BN 128
#define BK 8
#define TM 8
#define TN 8

__global__ __launch_bounds__(256)
void sgemm_nt(const float* __restrict__ A, const float* __restrict__ W,
              float* __restrict__ C) {
    __shared__ __align__(16) float As[BK][BM];
    __shared__ __align__(16) float Ws[BK][BN];
    const int bn = blockIdx.x * BN;
    const int bm = blockIdx.y * BM;
    const int t = threadIdx.x;          // 256 threads
    const int row = t >> 1;             // 0..127
    const int seg = (t & 1) * 4;        // 0 or 4
    const int tm = (t >> 4) * TM;       // 0..120
    const int tn = (t & 15) * TN;       // 0..120

    float acc[TM][TN];
#pragma unroll
    for (int i = 0; i < TM; i++)
#pragma unroll
        for (int j = 0; j < TN; j++) acc[i][j] = 0.f;

    const float* Ag = A + (size_t)(bm + row) * D + seg;
    const float* Wg = W + (size_t)(bn + row) * D + seg;

    for (int k0 = 0; k0 < D; k0 += BK) {
        float4 a4 = *(const float4*)(Ag + k0);
        float4 w4 = *(const float4*)(Wg + k0);
        As[seg + 0][row] = a4.x; As[seg + 1][row] = a4.y;
        As[seg + 2][row] = a4.z; As[seg + 3][row] = a4.w;
        Ws[seg + 0][row] = w4.x; Ws[seg + 1][row] = w4.y;
        Ws[seg + 2][row] = w4.z; Ws[seg + 3][row] = w4.w;
        __syncthreads();
#pragma unroll
        for (int kk = 0; kk < BK; kk++) {
            float4 a0 = *(const float4*)&As[kk][tm];
            float4 a1 = *(const float4*)&As[kk][tm + 4];
            float4 b0 = *(const float4*)&Ws[kk][tn];
            float4 b1 = *(const float4*)&Ws[kk][tn + 4];
            float ar[TM] = {a0.x, a0.y, a0.z, a0.w, a1.x, a1.y, a1.z, a1.w};
            float wr[TN] = {b0.x, b0.y, b0.z, b0.w, b1.x, b1.y, b1.z, b1.w};
#pragma unroll
            for (int i = 0; i < TM; i++)
#pragma unroll
                for (int j = 0; j < TN; j++) acc[i][j] += ar[i] * wr[j];
        }
        __syncthreads();
    }
#pragma unroll
    for (int i = 0; i < TM; i++) {
        float* crow = C + (size_t)(bm + tm + i) * D + bn + tn;
        float4 c0 = {acc[i][0], acc[i][1], acc[i][2], acc[i][3]};
        float4 c1 = {acc[i][4], acc[i][5], acc[i][6], acc[i][7]};
        *(float4*)(crow)     = c0;
        *(float4*)(crow + 4) = c1;
    }
}

// ---------------- block reduce (sum, sumsq) over 256 threads ---------------
__device__ __forceinline__ void blockReduce2(float& a, float& b, float* red) {
#pragma unroll
    for (int o = 16; o > 0; o >>= 1) {
        a += __shfl_down_sync(0xffffffffu, a, o);
        b += __shfl_down_sync(0xffffffffu, b, o);
    }
    int w = threadIdx.x >> 5, l = threadIdx.x & 31;
    if (l == 0) { red[w] = a; red[w + 8] = b; }
    __syncthreads();
    if (threadIdx.x == 0) {
        float sa = 0.f, sb = 0.f;
#pragma unroll
        for (int i = 0; i < 8; i++) { sa += red[i]; sb += red[i + 8]; }
        red[0] = sa; red[8] = sb;
    }
    __syncthreads();
    a = red[0]; b = red[8];
    __syncthreads();
}

// ---------------- write attention: slots attend over active modules --------
__global__ __launch_bounds__(256)
void write_attn_kernel(const float* __restrict__ workspace,
                       const float* __restrict__ gamma_ws,
                       const float* __restrict__ beta_ws) {
    const int b = blockIdx.x;
    const int t = threadIdx.x;  // 256
    __shared__ __align__(16) float Kw_s[KMOD * D];   // 16 KB
    __shared__ __align__(16) float Vw_s[KMOD * D];   // 16 KB
    __shared__ float probs[SSLOT][KMOD];
    __shared__ float red[16];

    const float4* Kg = (const float4*)(g_Kw + (size_t)b * KMOD * D);
    const float4* Vg = (const float4*)(g_Vw + (size_t)b * KMOD * D);
    float4* Ks4 = (float4*)Kw_s;
    float4* Vs4 = (float4*)Vw_s;
#pragma unroll
    for (int i = t; i < KMOD * D / 4; i += 256) { Ks4[i] = Kg[i]; Vs4[i] = Vg[i]; }
    __syncthreads();

    // scores: 32 (s,k) pairs, 8 lanes each, 64 elems per lane
    {
        int pair = t >> 3, sub = t & 7;
        int s = pair >> 3, k = pair & 7;
        const float* q  = g_Qw + s * D + sub * 64;
        const float* kk = Kw_s + k * D + sub * 64;
        float acc = 0.f;
#pragma unroll 8
        for (int j = 0; j < 64; j++) acc += q[j] * kk[j];
        acc += __shfl_down_sync(0xffffffffu, acc, 4);
        acc += __shfl_down_sync(0xffffffffu, acc, 2);
        acc += __shfl_down_sync(0xffffffffu, acc, 1);
        if (sub == 0) probs[s][k] = acc;   // already scaled via pre-scaled Qw
    }
    __syncthreads();

    // masked softmax over k, per slot s (threads 0..3)
    if (t < SSLOT) {
        int s = t;
        unsigned char act[KMOD];
        float m = -INFINITY;
#pragma unroll
        for (int k = 0; k < KMOD; k++) {
            act[k] = g_mask[b * KMOD + k];
            if (act[k] && probs[s][k] > m) m = probs[s][k];
        }
        float p[KMOD];
        if (m == -INFINITY) {              // all masked -> nan_to_num -> zeros
#pragma unroll
            for (int k = 0; k < KMOD; k++) p[k] = 0.f;
        } else {
            float sum = 0.f;
#pragma unroll
            for (int k = 0; k < KMOD; k++) {
                p[k] = act[k] ? __expf(probs[s][k] - m) : 0.f;
                sum += p[k];
            }
            float inv = 1.f / sum;
#pragma unroll
            for (int k = 0; k < KMOD; k++) p[k] *= inv;
        }
#pragma unroll
        for (int k = 0; k < KMOD; k++) probs[s][k] = p[k];
    }
    __syncthreads();

    // ws_upd[s,:] = LN(ws[s,:] + sum_k p[s,k] * Vw[b,k,:])
    for (int s = 0; s < SSLOT; s++) {
        float pk[KMOD];
#pragma unroll
        for (int k = 0; k < KMOD; k++) pk[k] = probs[s][k];
        int d0 = t, d1 = t + 256;
        float x0 = workspace[s * D + d0];
        float x1 = workspace[s * D + d1];
#pragma unroll
        for (int k = 0; k < KMOD; k++) {
            x0 += pk[k] * Vw_s[k * D + d0];
            x1 += pk[k] * Vw_s[k * D + d1];
        }
        float sum = x0 + x1, sq = x0 * x0 + x1 * x1;
        blockReduce2(sum, sq, red);
        float mean = sum * (1.f / D);
        float var  = sq * (1.f / D) - mean * mean;
        float rstd = rsqrtf(var + LN_EPS);
        size_t base = ((size_t)b * SSLOT + s) * D;
        g_wsupd[base + d0] = (x0 - mean) * rstd * gamma_ws[d0] + beta_ws[d0];
        g_wsupd[base + d1] = (x1 - mean) * rstd * gamma_ws[d1] + beta_ws[d1];
    }
}

// ---------------- read attention: modules read workspace -------------------
__global__ __launch_bounds__(256)
void read_attn_kernel() {
    const int b = blockIdx.x;
    const int t = threadIdx.x;  // 256
    __shared__ __align__(16) float Qr_s[KMOD * D];   // 16 KB
    __shared__ __align__(16) float Kr_s[SSLOT * D];  // 8 KB
    __shared__ __align__(16) float Vr_s[SSLOT * D];  // 8 KB
    __shared__ float probs[KMOD][SSLOT];

    const float4* Qg = (const float4*)(g_Qr + (size_t)b * KMOD * D);
    const float4* Kg = (const float4*)(g_Kr + (size_t)b * SSLOT * D);
    const float4* Vg = (const float4*)(g_Vr + (size_t)b * SSLOT * D);
    float4* Qs4 = (float4*)Qr_s;
    float4* Ks4 = (float4*)Kr_s;
    float4* Vs4 = (float4*)Vr_s;
#pragma unroll
    for (int i = t; i < KMOD * D / 4; i += 256) Qs4[i] = Qg[i];
#pragma unroll
    for (int i = t; i < SSLOT * D / 4; i += 256) { Ks4[i] = Kg[i]; Vs4[i] = Vg[i]; }
    __syncthreads();

    // scores: 32 (k,s) pairs
    {
        int pair = t >> 3, sub = t & 7;
        int k = pair >> 2, s = pair & 3;
        const float* q  = Qr_s + k * D + sub * 64;
        const float* kr = Kr_s + s * D + sub * 64;
        float acc = 0.f;
#pragma unroll 8
        for (int j = 0; j < 64; j++) acc += q[j] * kr[j];
        acc += __shfl_down_sync(0xffffffffu, acc, 4);
        acc += __shfl_down_sync(0xffffffffu, acc, 2);
        acc += __shfl_down_sync(0xffffffffu, acc, 1);
        if (sub == 0) probs[k][s] = acc * SCALE;
    }
    __syncthreads();

    // softmax over s (threads 0..7)
    if (t < KMOD) {
        int k = t;
        float m = probs[k][0];
#pragma unroll
        for (int s = 1; s < SSLOT; s++) m = fmaxf(m, probs[k][s]);
        float p[SSLOT];
        float sum = 0.f;
#pragma unroll
        for (int s = 0; s < SSLOT; s++) { p[s] = __expf(probs[k][s] - m); sum += p[s]; }
        float inv = 1.f / sum;
#pragma unroll
        for (int s = 0; s < SSLOT; s++) probs[k][s] = p[s] * inv;
    }
    __syncthreads();

    // broadcast[b,k,:] = sum_s p[k,s] * Vr[b,s,:]  -> reuse g_Kw
    for (int k = 0; k < KMOD; k++) {
        float p0 = probs[k][0], p1 = probs[k][1], p2 = probs[k][2], p3 = probs[k][3];
        int d0 = t, d1 = t + 256;
        float x0 = p0 * Vr_s[0 * D + d0] + p1 * Vr_s[1 * D + d0]
                 + p2 * Vr_s[2 * D + d0] + p3 * Vr_s[3 * D + d0];
        float x1 = p0 * Vr_s[0 * D + d1] + p1 * Vr_s[1 * D + d1]
                 + p2 * Vr_s[2 * D + d1] + p3 * Vr_s[3 * D + d1];
        size_t base = ((size_t)b * KMOD + k) * D;
        g_Kw[base + d0] = x0;
        g_Kw[base + d1] = x1;
    }
}

// ---------------- final: out = LN(hidden + proj) ---------------------------
__global__ __launch_bounds__(256)
void final_ln_kernel(const float* __restrict__ hidden,
                     const float* __restrict__ gamma_o,
                     const float* __restrict__ beta_o,
                     float* __restrict__ out) {
    const int r = blockIdx.x;          // 0..65535
    const int t = threadIdx.x;         // 256
    __shared__ float red[16];
    size_t base = (size_t)r * D;
    int d0 = t, d1 = t + 256;
    float x0 = hidden[base + d0] + g_Vw[base + d0];  // g_Vw holds proj
    float x1 = hidden[base + d1] + g_Vw[base + d1];
    float sum = x0 + x1, sq = x0 * x0 + x1 * x1;
    blockReduce2(sum, sq, red);
    float mean = sum * (1.f / D);
    float var  = sq * (1.f / D) - mean * mean;
    float rstd = rsqrtf(var + LN_EPS);
    out[base + d0] = (x0 - mean) * rstd * gamma_o[d0] + beta_o[d0];
    out[base + d1] = (x1 - mean) * rstd * gamma_o[d1] + beta_o[d1];
}

// ---------------- launch ---------------------------------------------------
extern "C" void kernel_launch(void* const* d_in, const int* in_sizes, int n_in,
                              void* d_out, int out_size) {
    const float*         hidden    = (const float*)d_in[0];
    const void*          maskraw   = (const void*)d_in[1];
    const float*         workspace = (const float*)d_in[2];
    const float*         Wq_w      = (const float*)d_in[3];
    const float*         Wk_w      = (const float*)d_in[4];
    const float*         Wv_w      = (const float*)d_in[5];
    const float*         Wq_r      = (const float*)d_in[6];
    const float*         Wk_r      = (const float*)d_in[7];
    const float*         Wv_r      = (const float*)d_in[8];
    const float*         Wo        = (const float*)d_in[9];
    const float*         gamma_ws  = (const float*)d_in[10];
    const float*         beta_ws   = (const float*)d_in[11];
    const float*         gamma_o   = (const float*)d_in[12];
    const float*         beta_o    = (const float*)d_in[13];
    float*               out       = (float*)d_out;

    float *pKw, *pVw, *pQr, *pWsu, *pKr, *pVr;
    cudaGetSymbolAddress((void**)&pKw,  g_Kw);
    cudaGetSymbolAddress((void**)&pVw,  g_Vw);
    cudaGetSymbolAddress((void**)&pQr,  g_Qr);
    cudaGetSymbolAddress((void**)&pWsu, g_wsupd);
    cudaGetSymbolAddress((void**)&pKr,  g_Kr);
    cudaGetSymbolAddress((void**)&pVr,  g_Vr);

    // mask dtype sniff + normalize to uint8
    mask_detect_kernel<<<1, 256>>>(maskraw);
    mask_convert_kernel<<<(BATCH * KMOD + 255) / 256, 256>>>(maskraw);

    // 0) batch-independent slot queries (pre-scaled)
    qw_kernel<<<SSLOT, D>>>(workspace, Wq_w);

    // 1) big projections from hidden
    dim3 gBig(D / BN, MBIG / BM);   // (4, 512)
    sgemm_nt<<<gBig, 256>>>(hidden, Wk_w, pKw);
    sgemm_nt<<<gBig, 256>>>(hidden, Wv_w, pVw);
    sgemm_nt<<<gBig, 256>>>(hidden, Wq_r, pQr);

    // 2) write attention + workspace LN
    write_attn_kernel<<<BATCH, 256>>>(workspace, gamma_ws, beta_ws);

    // 3) projections from updated workspace
    dim3 gWs(D / BN, MWS / BM);     // (4, 256)
    sgemm_nt<<<gWs, 256>>>(pWsu, Wk_r, pKr);
    sgemm_nt<<<gWs, 256>>>(pWsu, Wv_r, pVr);

    // 4) read attention -> broadcast (into g_Kw)
    read_attn_kernel<<<BATCH, 256>>>();

    // 5) output projection: proj = broadcast @ Wo^T (into g_Vw)
    sgemm_nt<<<gBig, 256>>>(pKw, Wo, pVw);

    // 6) residual + final LN -> out
    final_ln_kernel<<<MBIG, 256>>>(hidden, gamma_o, beta_o, out);
}

// round 8
// speedup vs baseline: 3.8791x; 3.8791x over previous
#include <cuda_runtime.h>
#include <cuda_fp16.h>
#include <math.h>
#include <stdint.h>

// Problem constants
#define D     512
#define KMOD  8
#define SSLOT 4
#define BATCH 8192
#define MBIG  (BATCH * KMOD)   // 65536
#define MWS   (BATCH * SSLOT)  // 32768
#define SCALE 0.04419417382415922f   // 512^-0.5
#define LN_EPS 1e-5f

// ---------------- scratch (device globals; allocation-free) ----------------
__device__ float g_Kw[(size_t)MBIG * D];
__device__ float g_Vw[(size_t)MBIG * D];     // later reused for 'proj'
__device__ float g_Qr[(size_t)MBIG * D];
__device__ float g_Kr[(size_t)MWS * D];
__device__ float g_Vr[(size_t)MWS * D];
__device__ __half g_half[(size_t)MBIG * D];  // fp16 GEMM A: hidden -> wsupd -> broadcast
__device__ __half g_w16[6 * (size_t)D * D];  // fp16 weights [n][k]
__device__ float g_Qw[SSLOT * D];            // pre-scaled slot queries
__device__ unsigned char g_mask[BATCH * KMOD];
__device__ int g_mask_is_i32;

// ---------------- helpers ---------------------------------------------------
__device__ __forceinline__ uint32_t smem_u32(const void* p) {
    uint32_t a;
    asm("{ .reg .u64 t; cvta.to.shared.u64 t, %1; cvt.u32.u64 %0, t; }"
        : "=r"(a) : "l"(p));
    return a;
}
__device__ __forceinline__ uint32_t sw128(uint32_t off) {
    return off ^ ((off >> 3) & 0x70);
}

// ---------------- mask dtype sniffing + normalization ----------------------
__global__ void mask_detect_kernel(const void* __restrict__ mask) {
    const int* mi = (const int*)mask;
    int bad = 0;
    for (int i = threadIdx.x; i < 16384; i += blockDim.x) {
        int v = mi[i];
        if (v != 0 && v != 1) bad = 1;
    }
    bad = __syncthreads_or(bad);
    if (threadIdx.x == 0) g_mask_is_i32 = !bad;
}
__global__ void mask_convert_kernel(const void* __restrict__ mask) {
    int i = blockIdx.x * blockDim.x + threadIdx.x;
    if (i >= BATCH * KMOD) return;
    unsigned char v;
    if (g_mask_is_i32) v = (((const int*)mask)[i] != 0);
    else               v = (((const unsigned char*)mask)[i] != 0);
    g_mask[i] = v;
}

// ---------------- fp32 -> fp16 conversion -----------------------------------
__global__ void to_half_kernel(const float* __restrict__ s,
                               __half* __restrict__ d, int n4) {
    int i = blockIdx.x * blockDim.x + threadIdx.x;
    if (i >= n4) return;
    float4 v = ((const float4*)s)[i];
    __half2* d2 = (__half2*)d;
    d2[i * 2]     = __floats2half2_rn(v.x, v.y);
    d2[i * 2 + 1] = __floats2half2_rn(v.z, v.w);
}

// ---------------- HMMA GEMM: C[M,512] = A[M,512] @ W[N,K]^T -----------------
// grid (nW, M/128, 4); 256 threads (8 warps: 4m x 2n), warp tile 32x64.
// SMEM: 2 stages x (A 128x64 half + W 128x64 half) = 64KB, SW128-swizzled.
#define GBM 128
#define GBN 128
#define GBK 64
#define TILE_BYTES (GBM * GBK * 2)          // 16384
#define STAGE_BYTES (2 * TILE_BYTES)        // 32768
#define GSMEM (2 * STAGE_BYTES)             // 65536

__global__ __launch_bounds__(256, 2)
void gemm_hmma(const __half* __restrict__ A,
               const __half* w0, float* c0,
               const __half* w1, float* c1,
               const __half* w2, float* c2) {
    extern __shared__ __align__(128) unsigned char sm[];
    uint32_t smb = smem_u32(sm);
    const int t = threadIdx.x;
    const int bw = blockIdx.x;
    const __half* W = (bw == 0) ? w0 : (bw == 1) ? w1 : w2;
    float* C = (bw == 0) ? c0 : (bw == 1) ? c1 : c2;
    const int bm = blockIdx.y * GBM;
    const int bn = blockIdx.z * GBN;
    const int lane = t & 31, wid = t >> 5;
    const int wm = (wid & 3) * 32;   // warp m offset
    const int wn = (wid >> 2) * 64;  // warp n offset

    float acc[2][8][4];
#pragma unroll
    for (int i = 0; i < 2; i++)
#pragma unroll
        for (int j = 0; j < 8; j++)
#pragma unroll
            for (int q = 0; q < 4; q++) acc[i][j][q] = 0.f;

    // --- stage issue: 1024 16B units each for A and W ---
    const int urow = t >> 1;                  // used for nothing; keep loader simple
    (void)urow;

#define ISSUE_STAGE(ko, buf)                                                      \
    do {                                                                          \
        uint32_t dA = smb + (buf) * STAGE_BYTES;                                  \
        uint32_t dW = dA + TILE_BYTES;                                            \
        const __half* sA = A + (size_t)bm * 512 + (ko) * GBK;                     \
        const __half* sW = W + (size_t)bn * 512 + (ko) * GBK;                     \
        _Pragma("unroll")                                                         \
        for (int q = 0; q < 4; q++) {                                             \
            int u = t + q * 256;                                                  \
            int row = u >> 3, cc = u & 7;                                         \
            size_t ga = __cvta_generic_to_global(sA + (size_t)row * 512 + cc * 8);\
            size_t gw = __cvta_generic_to_global(sW + (size_t)row * 512 + cc * 8);\
            uint32_t da = dA + sw128((uint32_t)(row * 128 + cc * 16));            \
            uint32_t dw = dW + sw128((uint32_t)(row * 128 + cc * 16));            \
            asm volatile("cp.async.cg.shared.global [%0], [%1], 16;" ::           \
                         "r"(da), "l"(ga));                                       \
            asm volatile("cp.async.cg.shared.global [%0], [%1], 16;" ::           \
                         "r"(dw), "l"(gw));                                       \
        }                                                                         \
        asm volatile("cp.async.commit_group;");                                   \
    } while (0)

    ISSUE_STAGE(0, 0);

    for (int ko = 0; ko < 8; ko++) {
        asm volatile("cp.async.wait_group 0;" ::: "memory");
        __syncthreads();
        if (ko < 7) ISSUE_STAGE(ko + 1, (ko + 1) & 1);
        uint32_t bufA = smb + (ko & 1) * STAGE_BYTES;
        uint32_t bufW = bufA + TILE_BYTES;

#pragma unroll
        for (int kk = 0; kk < 4; kk++) {
            // A fragments: two m16 tiles
            uint32_t a[2][4];
#pragma unroll
            for (int i = 0; i < 2; i++) {
                int row = wm + i * 16 + (lane & 7) + ((lane >> 3) & 1) * 8;
                int koff = kk * 16 + ((lane >> 4) & 1) * 8;
                uint32_t addr = bufA + sw128((uint32_t)(row * 128 + koff * 2));
                asm volatile(
                    "ldmatrix.sync.aligned.m8n8.x4.shared.b16 {%0,%1,%2,%3},[%4];"
                    : "=r"(a[i][0]), "=r"(a[i][1]), "=r"(a[i][2]), "=r"(a[i][3])
                    : "r"(addr));
            }
            // B fragments: 8 n8 tiles via 4 x4-ldmatrix
            uint32_t b[8][2];
#pragma unroll
            for (int jp = 0; jp < 4; jp++) {
                int row = wn + jp * 16 + ((lane >> 4) & 1) * 8 + (lane & 7);
                int koff = kk * 16 + ((lane >> 3) & 1) * 8;
                uint32_t addr = bufW + sw128((uint32_t)(row * 128 + koff * 2));
                uint32_t r0, r1, r2, r3;
                asm volatile(
                    "ldmatrix.sync.aligned.m8n8.x4.shared.b16 {%0,%1,%2,%3},[%4];"
                    : "=r"(r0), "=r"(r1), "=r"(r2), "=r"(r3) : "r"(addr));
                b[jp * 2][0] = r0; b[jp * 2][1] = r1;
                b[jp * 2 + 1][0] = r2; b[jp * 2 + 1][1] = r3;
            }
#pragma unroll
            for (int i = 0; i < 2; i++)
#pragma unroll
                for (int j = 0; j < 8; j++) {
                    asm volatile(
                        "mma.sync.aligned.m16n8k16.row.col.f32.f16.f16.f32 "
                        "{%0,%1,%2,%3},{%4,%5,%6,%7},{%8,%9},{%0,%1,%2,%3};"
                        : "+f"(acc[i][j][0]), "+f"(acc[i][j][1]),
                          "+f"(acc[i][j][2]), "+f"(acc[i][j][3])
                        : "r"(a[i][0]), "r"(a[i][1]), "r"(a[i][2]), "r"(a[i][3]),
                          "r"(b[j][0]), "r"(b[j][1]));
                }
        }
    }

    // epilogue: scatter accumulators to C (fp32)
#pragma unroll
    for (int i = 0; i < 2; i++) {
        int row = bm + wm + i * 16 + (lane >> 2);
#pragma unroll
        for (int j = 0; j < 8; j++) {
            int col = bn + wn + j * 8 + (lane & 3) * 2;
            float2 v01 = make_float2(acc[i][j][0], acc[i][j][1]);
            float2 v23 = make_float2(acc[i][j][2], acc[i][j][3]);
            *(float2*)(C + (size_t)row * 512 + col)       = v01;
            *(float2*)(C + (size_t)(row + 8) * 512 + col) = v23;
        }
    }
#undef ISSUE_STAGE
}

// ---------------- tiny precompute: Qw[s][e] = SCALE * sum_d ws[s,d]*Wq_w[e,d]
__global__ void qw_kernel(const float* __restrict__ workspace,
                          const float* __restrict__ Wq_w) {
    int s = blockIdx.x;
    int e = threadIdx.x;
    __shared__ float wsrow[D];
    wsrow[e] = workspace[s * D + e];
    __syncthreads();
    const float* wrow = Wq_w + (size_t)e * D;
    float acc = 0.f;
#pragma unroll 8
    for (int d = 0; d < D; d++) acc += wsrow[d] * wrow[d];
    g_Qw[s * D + e] = acc * SCALE;
}

// ---------------- block reduce (sum, sumsq) over 256 threads ---------------
__device__ __forceinline__ void blockReduce2(float& a, float& b, float* red) {
#pragma unroll
    for (int o = 16; o > 0; o >>= 1) {
        a += __shfl_down_sync(0xffffffffu, a, o);
        b += __shfl_down_sync(0xffffffffu, b, o);
    }
    int w = threadIdx.x >> 5, l = threadIdx.x & 31;
    if (l == 0) { red[w] = a; red[w + 8] = b; }
    __syncthreads();
    if (threadIdx.x == 0) {
        float sa = 0.f, sb = 0.f;
#pragma unroll
        for (int i = 0; i < 8; i++) { sa += red[i]; sb += red[i + 8]; }
        red[0] = sa; red[8] = sb;
    }
    __syncthreads();
    a = red[0]; b = red[8];
    __syncthreads();
}

// ---------------- write attention: slots attend over active modules --------
// writes ws_upd as fp16 into g_half (consumed only by the Kr/Vr GEMMs)
__global__ __launch_bounds__(256)
void write_attn_kernel(const float* __restrict__ workspace,
                       const float* __restrict__ gamma_ws,
                       const float* __restrict__ beta_ws) {
    const int b = blockIdx.x;
    const int t = threadIdx.x;
    __shared__ __align__(16) float Kw_s[KMOD * D];
    __shared__ __align__(16) float Vw_s[KMOD * D];
    __shared__ float probs[SSLOT][KMOD];
    __shared__ float red[16];

    const float4* Kg = (const float4*)(g_Kw + (size_t)b * KMOD * D);
    const float4* Vg = (const float4*)(g_Vw + (size_t)b * KMOD * D);
    float4* Ks4 = (float4*)Kw_s;
    float4* Vs4 = (float4*)Vw_s;
#pragma unroll
    for (int i = t; i < KMOD * D / 4; i += 256) { Ks4[i] = Kg[i]; Vs4[i] = Vg[i]; }
    __syncthreads();

    {
        int pair = t >> 3, sub = t & 7;
        int s = pair >> 3, k = pair & 7;
        const float* q  = g_Qw + s * D + sub * 64;
        const float* kk = Kw_s + k * D + sub * 64;
        float acc = 0.f;
#pragma unroll 8
        for (int j = 0; j < 64; j++) acc += q[j] * kk[j];
        acc += __shfl_down_sync(0xffffffffu, acc, 4);
        acc += __shfl_down_sync(0xffffffffu, acc, 2);
        acc += __shfl_down_sync(0xffffffffu, acc, 1);
        if (sub == 0) probs[s][k] = acc;
    }
    __syncthreads();

    if (t < SSLOT) {
        int s = t;
        unsigned char act[KMOD];
        float m = -INFINITY;
#pragma unroll
        for (int k = 0; k < KMOD; k++) {
            act[k] = g_mask[b * KMOD + k];
            if (act[k] && probs[s][k] > m) m = probs[s][k];
        }
        float p[KMOD];
        if (m == -INFINITY) {
#pragma unroll
            for (int k = 0; k < KMOD; k++) p[k] = 0.f;
        } else {
            float sum = 0.f;
#pragma unroll
            for (int k = 0; k < KMOD; k++) {
                p[k] = act[k] ? __expf(probs[s][k] - m) : 0.f;
                sum += p[k];
            }
            float inv = 1.f / sum;
#pragma unroll
            for (int k = 0; k < KMOD; k++) p[k] *= inv;
        }
#pragma unroll
        for (int k = 0; k < KMOD; k++) probs[s][k] = p[k];
    }
    __syncthreads();

    for (int s = 0; s < SSLOT; s++) {
        float pk[KMOD];
#pragma unroll
        for (int k = 0; k < KMOD; k++) pk[k] = probs[s][k];
        int d0 = t, d1 = t + 256;
        float x0 = workspace[s * D + d0];
        float x1 = workspace[s * D + d1];
#pragma unroll
        for (int k = 0; k < KMOD; k++) {
            x0 += pk[k] * Vw_s[k * D + d0];
            x1 += pk[k] * Vw_s[k * D + d1];
        }
        float sum = x0 + x1, sq = x0 * x0 + x1 * x1;
        blockReduce2(sum, sq, red);
        float mean = sum * (1.f / D);
        float var  = sq * (1.f / D) - mean * mean;
        float rstd = rsqrtf(var + LN_EPS);
        size_t base = ((size_t)b * SSLOT + s) * D;
        g_half[base + d0] = __float2half_rn((x0 - mean) * rstd * gamma_ws[d0] + beta_ws[d0]);
        g_half[base + d1] = __float2half_rn((x1 - mean) * rstd * gamma_ws[d1] + beta_ws[d1]);
    }
}

// ---------------- read attention: modules read workspace -------------------
// reads fp32 Qr/Kr/Vr, writes broadcast as fp16 into g_half (GEMM input)
__global__ __launch_bounds__(256)
void read_attn_kernel() {
    const int b = blockIdx.x;
    const int t = threadIdx.x;
    __shared__ __align__(16) float Qr_s[KMOD * D];
    __shared__ __align__(16) float Kr_s[SSLOT * D];
    __shared__ __align__(16) float Vr_s[SSLOT * D];
    __shared__ float probs[KMOD][SSLOT];

    const float4* Qg = (const float4*)(g_Qr + (size_t)b * KMOD * D);
    const float4* Kg = (const float4*)(g_Kr + (size_t)b * SSLOT * D);
    const float4* Vg = (const float4*)(g_Vr + (size_t)b * SSLOT * D);
    float4* Qs4 = (float4*)Qr_s;
    float4* Ks4 = (float4*)Kr_s;
    float4* Vs4 = (float4*)Vr_s;
#pragma unroll
    for (int i = t; i < KMOD * D / 4; i += 256) Qs4[i] = Qg[i];
#pragma unroll
    for (int i = t; i < SSLOT * D / 4; i += 256) { Ks4[i] = Kg[i]; Vs4[i] = Vg[i]; }
    __syncthreads();

    {
        int pair = t >> 3, sub = t & 7;
        int k = pair >> 2, s = pair & 3;
        const float* q  = Qr_s + k * D + sub * 64;
        const float* kr = Kr_s + s * D + sub * 64;
        float acc = 0.f;
#pragma unroll 8
        for (int j = 0; j < 64; j++) acc += q[j] * kr[j];
        acc += __shfl_down_sync(0xffffffffu, acc, 4);
        acc += __shfl_down_sync(0xffffffffu, acc, 2);
        acc += __shfl_down_sync(0xffffffffu, acc, 1);
        if (sub == 0) probs[k][s] = acc * SCALE;
    }
    __syncthreads();

    if (t < KMOD) {
        int k = t;
        float m = probs[k][0];
#pragma unroll
        for (int s = 1; s < SSLOT; s++) m = fmaxf(m, probs[k][s]);
        float p[SSLOT];
        float sum = 0.f;
#pragma unroll
        for (int s = 0; s < SSLOT; s++) { p[s] = __expf(probs[k][s] - m); sum += p[s]; }
        float inv = 1.f / sum;
#pragma unroll
        for (int s = 0; s < SSLOT; s++) probs[k][s] = p[s] * inv;
    }
    __syncthreads();

    for (int k = 0; k < KMOD; k++) {
        float p0 = probs[k][0], p1 = probs[k][1], p2 = probs[k][2], p3 = probs[k][3];
        int d0 = t, d1 = t + 256;
        float x0 = p0 * Vr_s[0 * D + d0] + p1 * Vr_s[1 * D + d0]
                 + p2 * Vr_s[2 * D + d0] + p3 * Vr_s[3 * D + d0];
        float x1 = p0 * Vr_s[0 * D + d1] + p1 * Vr_s[1 * D + d1]
                 + p2 * Vr_s[2 * D + d1] + p3 * Vr_s[3 * D + d1];
        size_t base = ((size_t)b * KMOD + k) * D;
        g_half[base + d0] = __float2half_rn(x0);
        g_half[base + d1] = __float2half_rn(x1);
    }
}

// ---------------- final: out = LN(hidden + proj) ---------------------------
__global__ __launch_bounds__(256)
void final_ln_kernel(const float* __restrict__ hidden,
                     const float* __restrict__ gamma_o,
                     const float* __restrict__ beta_o,
                     float* __restrict__ out) {
    const int r = blockIdx.x;
    const int t = threadIdx.x;
    __shared__ float red[16];
    size_t base = (size_t)r * D;
    int d0 = t, d1 = t + 256;
    float x0 = hidden[base + d0] + g_Vw[base + d0];  // g_Vw holds proj
    float x1 = hidden[base + d1] + g_Vw[base + d1];
    float sum = x0 + x1, sq = x0 * x0 + x1 * x1;
    blockReduce2(sum, sq, red);
    float mean = sum * (1.f / D);
    float var  = sq * (1.f / D) - mean * mean;
    float rstd = rsqrtf(var + LN_EPS);
    out[base + d0] = (x0 - mean) * rstd * gamma_o[d0] + beta_o[d0];
    out[base + d1] = (x1 - mean) * rstd * gamma_o[d1] + beta_o[d1];
}

// ---------------- launch ---------------------------------------------------
extern "C" void kernel_launch(void* const* d_in, const int* in_sizes, int n_in,
                              void* d_out, int out_size) {
    const float* hidden    = (const float*)d_in[0];
    const void*  maskraw   = (const void*)d_in[1];
    const float* workspace = (const float*)d_in[2];
    const float* Wq_w      = (const float*)d_in[3];
    const float* Wk_w      = (const float*)d_in[4];
    const float* Wv_w      = (const float*)d_in[5];
    const float* Wq_r      = (const float*)d_in[6];
    const float* Wk_r      = (const float*)d_in[7];
    const float* Wv_r      = (const float*)d_in[8];
    const float* Wo        = (const float*)d_in[9];
    const float* gamma_ws  = (const float*)d_in[10];
    const float* beta_ws   = (const float*)d_in[11];
    const float* gamma_o   = (const float*)d_in[12];
    const float* beta_o    = (const float*)d_in[13];
    float*       out       = (float*)d_out;

    float *pKw, *pVw, *pQr, *pKr, *pVr;
    __half *pH, *pW16;
    cudaGetSymbolAddress((void**)&pKw,  g_Kw);
    cudaGetSymbolAddress((void**)&pVw,  g_Vw);
    cudaGetSymbolAddress((void**)&pQr,  g_Qr);
    cudaGetSymbolAddress((void**)&pKr,  g_Kr);
    cudaGetSymbolAddress((void**)&pVr,  g_Vr);
    cudaGetSymbolAddress((void**)&pH,   g_half);
    cudaGetSymbolAddress((void**)&pW16, g_w16);

    cudaFuncSetAttribute(gemm_hmma,
                         cudaFuncAttributeMaxDynamicSharedMemorySize, GSMEM);

    // weight slots: 0=Wk_w 1=Wv_w 2=Wq_r 3=Wk_r 4=Wv_r 5=Wo
    const float* wsrc[6] = {Wk_w, Wv_w, Wq_r, Wk_r, Wv_r, Wo};
    __half* w16[6];
    for (int i = 0; i < 6; i++) w16[i] = pW16 + (size_t)i * D * D;

    // mask dtype sniff + normalize
    mask_detect_kernel<<<1, 256>>>(maskraw);
    mask_convert_kernel<<<(BATCH * KMOD + 255) / 256, 256>>>(maskraw);

    // weights -> fp16
    for (int i = 0; i < 6; i++)
        to_half_kernel<<<(D * D / 4 + 255) / 256, 256>>>(wsrc[i], w16[i], D * D / 4);

    // batch-independent slot queries (pre-scaled, fp32)
    qw_kernel<<<SSLOT, D>>>(workspace, Wq_w);

    // hidden -> fp16 (L2-resident GEMM A)
    to_half_kernel<<<((int)((size_t)MBIG * D / 4) + 255) / 256, 256>>>(
        hidden, pH, (int)((size_t)MBIG * D / 4));

    // big projections from hidden: Kw, Vw, Qr
    gemm_hmma<<<dim3(3, MBIG / GBM, 4), 256, GSMEM>>>(
        pH, w16[0], pKw, w16[1], pVw, w16[2], pQr);

    // write attention + workspace LN (-> g_half as fp16)
    write_attn_kernel<<<BATCH, 256>>>(workspace, gamma_ws, beta_ws);

    // projections from updated workspace: Kr, Vr
    gemm_hmma<<<dim3(2, MWS / GBM, 4), 256, GSMEM>>>(
        pH, w16[3], pKr, w16[4], pVr, w16[4], pVr);

    // read attention -> broadcast (fp16 into g_half)
    read_attn_kernel<<<BATCH, 256>>>();

    // output projection: proj = broadcast @ Wo^T -> g_Vw
    gemm_hmma<<<dim3(1, MBIG / GBM, 4), 256, GSMEM>>>(
        pH, w16[5], pVw, w16[5], pVw, w16[5], pVw);

    // residual + final LN -> out
    final_ln_kernel<<<MBIG, 256>>>(hidden, gamma_o, beta_o, out);
}